// round 2
// baseline (speedup 1.0000x reference)
#include <cuda_runtime.h>
#include <cuda_fp16.h>
#include <cstdint>

// ============================================================================
// y[8192,4096] = x[8192,4096] @ sign(W)[4096,4096], fp32 in/out.
// Harness compiles for PLAIN sm_103 (no 'a' features): no tcgen05, no TMA tile.
// Fallback: Ampere-style GEMM — cp.async 3-stage pipeline + ldmatrix +
// mma.sync.m16n8k16 (fp16 inputs, fp32 accumulate).
// sign(W) is exact in fp16; only x is rounded -> rel_err ~2.5e-4.
// ============================================================================

#define MM 8192
#define NN 4096
#define KK 4096

#define TM 128
#define TN 128
#define TK 64                      // K elements per stage (128 bytes per row)
#define NSTAGE 3
#define NK (KK / TK)               // 64

#define STAGE_BYTES (TM * TK * 2)  // 16384 per operand per stage
#define SMEM_TOTAL (2 * NSTAGE * STAGE_BYTES)  // 98304

// Scratch (static device arrays: allocation-free per harness rules)
__device__ __align__(1024) __half g_xh[(size_t)MM * KK];   // x as fp16, [M][K]
__device__ __align__(1024) __half g_sh[(size_t)NN * KK];   // sign(W)^T fp16, [N][K]

// ---------------------------------------------------------------------------
// PTX helpers (all plain-sm_80/90 features)
// ---------------------------------------------------------------------------
__device__ __forceinline__ uint32_t smem_u32(const void* p) {
    uint32_t a;
    asm("{ .reg .u64 t; cvta.to.shared.u64 t, %1; cvt.u32.u64 %0, t; }"
        : "=r"(a) : "l"(p));
    return a;
}

#define CP_ASYNC_CG(dst, src) \
    asm volatile("cp.async.cg.shared.global [%0], [%1], 16;" \
        :: "r"((uint32_t)(dst)), "l"(src) : "memory")
#define CP_COMMIT() asm volatile("cp.async.commit_group;" ::: "memory")
#define CP_WAIT(n)  asm volatile("cp.async.wait_group %0;" :: "n"(n) : "memory")

__device__ __forceinline__ void ldsm4(uint32_t* r, uint32_t addr) {
    asm volatile("ldmatrix.sync.aligned.m8n8.x4.shared.b16 {%0,%1,%2,%3}, [%4];"
        : "=r"(r[0]), "=r"(r[1]), "=r"(r[2]), "=r"(r[3]) : "r"(addr));
}

__device__ __forceinline__ void mma16816(float* c, const uint32_t* a, const uint32_t* b) {
    asm volatile(
        "mma.sync.aligned.m16n8k16.row.col.f32.f16.f16.f32 "
        "{%0,%1,%2,%3}, {%4,%5,%6,%7}, {%8,%9}, {%0,%1,%2,%3};"
        : "+f"(c[0]), "+f"(c[1]), "+f"(c[2]), "+f"(c[3])
        : "r"(a[0]), "r"(a[1]), "r"(a[2]), "r"(a[3]), "r"(b[0]), "r"(b[1]));
}

// ---------------------------------------------------------------------------
// Conversion kernels
// ---------------------------------------------------------------------------
struct h4_t { __half2 a, b; };

__global__ void k_cvt_x(const float4* __restrict__ x, h4_t* __restrict__ o, int n4) {
    int i = blockIdx.x * blockDim.x + threadIdx.x;
    if (i < n4) {
        float4 v = x[i];
        h4_t h;
        h.a = __floats2half2_rn(v.x, v.y);
        h.b = __floats2half2_rn(v.z, v.w);
        o[i] = h;
    }
}

// o[n][k] = sign(W[k][n]) as fp16, via 32x32 SMEM transpose tiles
__global__ void k_sign_t(const float* __restrict__ W, __half* __restrict__ o) {
    __shared__ float t[32][33];
    int n0 = blockIdx.x * 32, k0 = blockIdx.y * 32;
    int tx = threadIdx.x, ty = threadIdx.y;
#pragma unroll
    for (int j = 0; j < 32; j += 8)
        t[ty + j][tx] = W[(size_t)(k0 + ty + j) * NN + n0 + tx];
    __syncthreads();
#pragma unroll
    for (int j = 0; j < 32; j += 8) {
        float v = t[tx][ty + j];
        float s = (v > 0.f) ? 1.f : ((v < 0.f) ? -1.f : 0.f);
        o[(size_t)(n0 + ty + j) * KK + k0 + tx] = __float2half(s);
    }
}

// ---------------------------------------------------------------------------
// GEMM: 128x128 CTA tile, 8 warps (4x2), warp tile 32x64, 3-stage cp.async
// ---------------------------------------------------------------------------
__global__ __launch_bounds__(256) void gemm_kernel(float* __restrict__ out) {
    extern __shared__ char smem[];
    const uint32_t sA0 = smem_u32(smem);
    const uint32_t sB0 = sA0 + NSTAGE * STAGE_BYTES;

    const int tid = threadIdx.x;
    const int wid = tid >> 5;
    const int lane = tid & 31;
    const int wm = wid & 3;        // 0..3  (M direction, 32 rows each)
    const int wn = wid >> 2;       // 0..1  (N direction, 64 cols each)

    // L2-friendly tile mapping: GROUP_M=8 along M, sweep N within group
    const int TILES_N = NN / TN;   // 32
    const int GROUP_M = 8;
    int bid = blockIdx.x;
    int group = bid / (GROUP_M * TILES_N);
    int rem = bid % (GROUP_M * TILES_N);
    int pm = group * GROUP_M + (rem % GROUP_M);
    int pn = rem / GROUP_M;
    const int m0 = pm * TM;
    const int n0 = pn * TN;

    const __half* gA = g_xh + (size_t)m0 * KK;
    const __half* gB = g_sh + (size_t)n0 * KK;

    // --- stage loader: 128 rows x 128B each for A and B ---
    // thread t loads chunk idx = t + i*256: row = idx/8, 16B chunk c = idx%8,
    // swizzled store chunk = c ^ (row & 7)
    auto load_stage = [&](int s, int it) {
        uint32_t sa = sA0 + s * STAGE_BYTES;
        uint32_t sb = sB0 + s * STAGE_BYTES;
        const __half* ga = gA + (size_t)it * TK;
        const __half* gb = gB + (size_t)it * TK;
#pragma unroll
        for (int i = 0; i < 4; ++i) {
            int idx = tid + i * 256;
            int row = idx >> 3, c = idx & 7;
            int sc = c ^ (row & 7);
            CP_ASYNC_CG(sa + row * 128 + sc * 16, ga + (size_t)row * KK + c * 8);
            CP_ASYNC_CG(sb + row * 128 + sc * 16, gb + (size_t)row * KK + c * 8);
        }
    };

    float acc[2][8][4];
#pragma unroll
    for (int mt = 0; mt < 2; ++mt)
#pragma unroll
        for (int nf = 0; nf < 8; ++nf)
#pragma unroll
            for (int v = 0; v < 4; ++v) acc[mt][nf][v] = 0.f;

    // prologue: fill NSTAGE-1 stages
#pragma unroll
    for (int s = 0; s < NSTAGE - 1; ++s) {
        load_stage(s, s);
        CP_COMMIT();
    }

    for (int it = 0; it < NK; ++it) {
        CP_WAIT(NSTAGE - 2);
        __syncthreads();

        // refill the stage freed in the previous iteration
        int nx = it + NSTAGE - 1;
        if (nx < NK) load_stage(nx % NSTAGE, nx);
        CP_COMMIT();

        const int s = it % NSTAGE;
        const uint32_t sa = sA0 + s * STAGE_BYTES;
        const uint32_t sb = sB0 + s * STAGE_BYTES;

#pragma unroll
        for (int ks = 0; ks < 4; ++ks) {
            uint32_t a[2][4];
#pragma unroll
            for (int mt = 0; mt < 2; ++mt) {
                int row = wm * 32 + mt * 16 + (lane & 15);
                int ch = ks * 2 + (lane >> 4);
                ldsm4(a[mt], sa + row * 128 + ((ch ^ (row & 7)) << 4));
            }
            uint32_t b[4][4];
#pragma unroll
            for (int bq = 0; bq < 4; ++bq) {
                int n = wn * 64 + bq * 16 + (lane & 7) + ((lane >> 4) << 3);
                int ch = ks * 2 + ((lane >> 3) & 1);
                ldsm4(b[bq], sb + n * 128 + ((ch ^ (n & 7)) << 4));
            }
#pragma unroll
            for (int mt = 0; mt < 2; ++mt)
#pragma unroll
                for (int nf = 0; nf < 8; ++nf)
                    mma16816(acc[mt][nf], a[mt], &b[nf >> 1][(nf & 1) * 2]);
        }
        __syncthreads();
    }

    // --- epilogue: direct float2 stores ---
#pragma unroll
    for (int mt = 0; mt < 2; ++mt) {
        int r0 = m0 + wm * 32 + mt * 16 + (lane >> 2);
#pragma unroll
        for (int nf = 0; nf < 8; ++nf) {
            int c0 = n0 + wn * 64 + nf * 8 + (lane & 3) * 2;
            float2 v0 = make_float2(acc[mt][nf][0], acc[mt][nf][1]);
            float2 v1 = make_float2(acc[mt][nf][2], acc[mt][nf][3]);
            *reinterpret_cast<float2*>(out + (size_t)r0 * NN + c0) = v0;
            *reinterpret_cast<float2*>(out + (size_t)(r0 + 8) * NN + c0) = v1;
        }
    }
}

// ---------------------------------------------------------------------------
// Host launcher
// ---------------------------------------------------------------------------
extern "C" void kernel_launch(void* const* d_in, const int* in_sizes, int n_in,
                              void* d_out, int out_size) {
    const float* x;
    const float* W;
    if (in_sizes[0] == MM * KK) {
        x = (const float*)d_in[0];
        W = (const float*)d_in[1];
    } else {
        x = (const float*)d_in[1];
        W = (const float*)d_in[0];
    }

    void* xh_ptr = nullptr;
    void* sh_ptr = nullptr;
    cudaGetSymbolAddress(&xh_ptr, g_xh);
    cudaGetSymbolAddress(&sh_ptr, g_sh);

    // conversions
    {
        int n4 = MM * KK / 4;
        k_cvt_x<<<(n4 + 255) / 256, 256>>>((const float4*)x, (h4_t*)xh_ptr, n4);
        dim3 g(NN / 32, KK / 32), b(32, 8);
        k_sign_t<<<g, b>>>(W, (__half*)sh_ptr);
    }

    // GEMM
    cudaFuncSetAttribute(gemm_kernel, cudaFuncAttributeMaxDynamicSharedMemorySize, SMEM_TOTAL);
    int n_tiles = (MM / TM) * (NN / TN);   // 2048
    gemm_kernel<<<n_tiles, 256, SMEM_TOTAL>>>((float*)d_out);
}

// round 3
// speedup vs baseline: 1.0265x; 1.0265x over previous
#include <cuda_runtime.h>
#include <cuda_fp16.h>
#include <cstdint>

// ============================================================================
// y[8192,4096] = x[8192,4096] @ sign(W)[4096,4096], fp32 in/out.
// Plain-sm_103 target (no tcgen05). Ampere-style pipelined HMMA GEMM:
// cp.async 3-stage + ldmatrix + mma.sync.m16n8k16 (fp16 in, fp32 acc).
// R3: CTA tile 128x256, warp tile 64x64 — halves smem-crossbar bytes per MMA
// (prev config was LDS-bound: 128KB smem traffic vs 512 HMMA per stage).
// ============================================================================

#define MM 8192
#define NN 4096
#define KK 4096

#define TM 128
#define TN 256
#define TK 64                      // K elems per stage (128B per row)
#define NSTAGE 3
#define NK (KK / TK)               // 64

#define A_STAGE_BYTES (TM * TK * 2)            // 16384
#define B_STAGE_BYTES (TN * TK * 2)            // 32768
#define SMEM_TOTAL (NSTAGE * (A_STAGE_BYTES + B_STAGE_BYTES))  // 147456

// Scratch (static device arrays: allocation-free per harness rules)
__device__ __align__(1024) __half g_xh[(size_t)MM * KK];   // x as fp16, [M][K]
__device__ __align__(1024) __half g_sh[(size_t)NN * KK];   // sign(W)^T fp16, [N][K]

// ---------------------------------------------------------------------------
// PTX helpers
// ---------------------------------------------------------------------------
__device__ __forceinline__ uint32_t smem_u32(const void* p) {
    uint32_t a;
    asm("{ .reg .u64 t; cvta.to.shared.u64 t, %1; cvt.u32.u64 %0, t; }"
        : "=r"(a) : "l"(p));
    return a;
}

#define CP_ASYNC_CG(dst, src) \
    asm volatile("cp.async.cg.shared.global [%0], [%1], 16;" \
        :: "r"((uint32_t)(dst)), "l"(src) : "memory")
#define CP_COMMIT() asm volatile("cp.async.commit_group;" ::: "memory")
#define CP_WAIT(n)  asm volatile("cp.async.wait_group %0;" :: "n"(n) : "memory")

__device__ __forceinline__ void ldsm4(uint32_t* r, uint32_t addr) {
    asm volatile("ldmatrix.sync.aligned.m8n8.x4.shared.b16 {%0,%1,%2,%3}, [%4];"
        : "=r"(r[0]), "=r"(r[1]), "=r"(r[2]), "=r"(r[3]) : "r"(addr));
}

__device__ __forceinline__ void mma16816(float* c, const uint32_t* a, const uint32_t* b) {
    asm volatile(
        "mma.sync.aligned.m16n8k16.row.col.f32.f16.f16.f32 "
        "{%0,%1,%2,%3}, {%4,%5,%6,%7}, {%8,%9}, {%0,%1,%2,%3};"
        : "+f"(c[0]), "+f"(c[1]), "+f"(c[2]), "+f"(c[3])
        : "r"(a[0]), "r"(a[1]), "r"(a[2]), "r"(a[3]), "r"(b[0]), "r"(b[1]));
}

// ---------------------------------------------------------------------------
// Conversion kernels
// ---------------------------------------------------------------------------
struct h8_t { __half2 a, b, c, d; };   // 16B

__global__ void k_cvt_x(const float4* __restrict__ x, h8_t* __restrict__ o, int n8) {
    int i = blockIdx.x * blockDim.x + threadIdx.x;
    if (i < n8) {
        float4 v0 = x[2 * i];
        float4 v1 = x[2 * i + 1];
        h8_t h;
        h.a = __floats2half2_rn(v0.x, v0.y);
        h.b = __floats2half2_rn(v0.z, v0.w);
        h.c = __floats2half2_rn(v1.x, v1.y);
        h.d = __floats2half2_rn(v1.z, v1.w);
        o[i] = h;
    }
}

// o[n][k] = sign(W[k][n]) as fp16, via 32x32 SMEM transpose tiles
__global__ void k_sign_t(const float* __restrict__ W, __half* __restrict__ o) {
    __shared__ float t[32][33];
    int n0 = blockIdx.x * 32, k0 = blockIdx.y * 32;
    int tx = threadIdx.x, ty = threadIdx.y;
#pragma unroll
    for (int j = 0; j < 32; j += 8)
        t[ty + j][tx] = W[(size_t)(k0 + ty + j) * NN + n0 + tx];
    __syncthreads();
#pragma unroll
    for (int j = 0; j < 32; j += 8) {
        float v = t[tx][ty + j];
        float s = (v > 0.f) ? 1.f : ((v < 0.f) ? -1.f : 0.f);
        o[(size_t)(n0 + ty + j) * KK + k0 + tx] = __float2half(s);
    }
}

// ---------------------------------------------------------------------------
// GEMM: 128x256 CTA tile, 8 warps (2M x 4N), warp tile 64x64, 3-stage cp.async
// ---------------------------------------------------------------------------
__global__ __launch_bounds__(256, 1) void gemm_kernel(float* __restrict__ out) {
    extern __shared__ char smem[];
    const uint32_t sA0 = smem_u32(smem);
    const uint32_t sB0 = sA0 + NSTAGE * A_STAGE_BYTES;

    const int tid = threadIdx.x;
    const int wid = tid >> 5;
    const int lane = tid & 31;
    const int wm = wid & 1;        // 0..1  (M direction, 64 rows each)
    const int wn = wid >> 1;       // 0..3  (N direction, 64 cols each)

    // L2-friendly tile mapping: GROUP_M=8 along M, sweep N within group
    const int TILES_N = NN / TN;   // 16
    const int GROUP_M = 8;
    int bid = blockIdx.x;
    int group = bid / (GROUP_M * TILES_N);
    int rem = bid % (GROUP_M * TILES_N);
    int pm = group * GROUP_M + (rem % GROUP_M);
    int pn = rem / GROUP_M;
    const int m0 = pm * TM;
    const int n0 = pn * TN;

    const __half* gA = g_xh + (size_t)m0 * KK;
    const __half* gB = g_sh + (size_t)n0 * KK;

    // stage loader: A 128 rows, B 256 rows, 128B per row, XOR-swizzled chunks
    auto load_stage = [&](int s, int it) {
        uint32_t sa = sA0 + s * A_STAGE_BYTES;
        uint32_t sb = sB0 + s * B_STAGE_BYTES;
        const __half* ga = gA + (size_t)it * TK;
        const __half* gb = gB + (size_t)it * TK;
#pragma unroll
        for (int i = 0; i < 4; ++i) {                 // A: 1024 chunks
            int idx = tid + i * 256;
            int row = idx >> 3, c = idx & 7;
            int sc = c ^ (row & 7);
            CP_ASYNC_CG(sa + row * 128 + sc * 16, ga + (size_t)row * KK + c * 8);
        }
#pragma unroll
        for (int i = 0; i < 8; ++i) {                 // B: 2048 chunks
            int idx = tid + i * 256;
            int row = idx >> 3, c = idx & 7;
            int sc = c ^ (row & 7);
            CP_ASYNC_CG(sb + row * 128 + sc * 16, gb + (size_t)row * KK + c * 8);
        }
    };

    float acc[4][8][4];
#pragma unroll
    for (int mt = 0; mt < 4; ++mt)
#pragma unroll
        for (int nf = 0; nf < 8; ++nf)
#pragma unroll
            for (int v = 0; v < 4; ++v) acc[mt][nf][v] = 0.f;

    // prologue
#pragma unroll
    for (int s = 0; s < NSTAGE - 1; ++s) {
        load_stage(s, s);
        CP_COMMIT();
    }

    for (int it = 0; it < NK; ++it) {
        CP_WAIT(NSTAGE - 2);
        __syncthreads();

        int nx = it + NSTAGE - 1;
        if (nx < NK) load_stage(nx % NSTAGE, nx);
        CP_COMMIT();

        const int s = it % NSTAGE;
        const uint32_t sa = sA0 + s * A_STAGE_BYTES;
        const uint32_t sb = sB0 + s * B_STAGE_BYTES;

#pragma unroll
        for (int ks = 0; ks < 4; ++ks) {
            uint32_t a[4][4];
#pragma unroll
            for (int mt = 0; mt < 4; ++mt) {
                int row = wm * 64 + mt * 16 + (lane & 15);
                int ch = ks * 2 + (lane >> 4);
                ldsm4(a[mt], sa + row * 128 + ((ch ^ (row & 7)) << 4));
            }
            uint32_t b[4][4];
#pragma unroll
            for (int bq = 0; bq < 4; ++bq) {
                int n = wn * 64 + bq * 16 + (lane & 7) + ((lane >> 4) << 3);
                int ch = ks * 2 + ((lane >> 3) & 1);
                ldsm4(b[bq], sb + n * 128 + ((ch ^ (n & 7)) << 4));
            }
#pragma unroll
            for (int mt = 0; mt < 4; ++mt)
#pragma unroll
                for (int nf = 0; nf < 8; ++nf)
                    mma16816(acc[mt][nf], a[mt], &b[nf >> 1][(nf & 1) * 2]);
        }
        __syncthreads();
    }

    // epilogue: direct float2 stores
#pragma unroll
    for (int mt = 0; mt < 4; ++mt) {
        int r0 = m0 + wm * 64 + mt * 16 + (lane >> 2);
#pragma unroll
        for (int nf = 0; nf < 8; ++nf) {
            int c0 = n0 + wn * 64 + nf * 8 + (lane & 3) * 2;
            float2 v0 = make_float2(acc[mt][nf][0], acc[mt][nf][1]);
            float2 v1 = make_float2(acc[mt][nf][2], acc[mt][nf][3]);
            *reinterpret_cast<float2*>(out + (size_t)r0 * NN + c0) = v0;
            *reinterpret_cast<float2*>(out + (size_t)(r0 + 8) * NN + c0) = v1;
        }
    }
}

// ---------------------------------------------------------------------------
// Host launcher
// ---------------------------------------------------------------------------
extern "C" void kernel_launch(void* const* d_in, const int* in_sizes, int n_in,
                              void* d_out, int out_size) {
    const float* x;
    const float* W;
    if (in_sizes[0] == MM * KK) {
        x = (const float*)d_in[0];
        W = (const float*)d_in[1];
    } else {
        x = (const float*)d_in[1];
        W = (const float*)d_in[0];
    }

    void* xh_ptr = nullptr;
    void* sh_ptr = nullptr;
    cudaGetSymbolAddress(&xh_ptr, g_xh);
    cudaGetSymbolAddress(&sh_ptr, g_sh);

    // conversions
    {
        int n8 = MM * KK / 8;
        k_cvt_x<<<(n8 + 255) / 256, 256>>>((const float4*)x, (h8_t*)xh_ptr, n8);
        dim3 g(NN / 32, KK / 32), b(32, 8);
        k_sign_t<<<g, b>>>(W, (__half*)sh_ptr);
    }

    // GEMM
    cudaFuncSetAttribute(gemm_kernel, cudaFuncAttributeMaxDynamicSharedMemorySize, SMEM_TOTAL);
    int n_tiles = (MM / TM) * (NN / TN);   // 1024
    gemm_kernel<<<n_tiles, 256, SMEM_TOTAL>>>((float*)d_out);
}

// round 4
// speedup vs baseline: 1.0326x; 1.0059x over previous
#include <cuda_runtime.h>
#include <cuda_fp16.h>
#include <cstdint>

// ============================================================================
// y[8192,4096] = x[8192,4096] @ sign(W)[4096,4096], fp32 in/out.
// Plain-sm_103 target (no tcgen05). Ampere-style pipelined HMMA GEMM.
// R4: single sync/iter + ks-level fragment double-buffering (probe whether
// we sit on the legacy-HMMA pipe floor or have dependency stalls).
// ============================================================================

#define MM 8192
#define NN 4096
#define KK 4096

#define TM 128
#define TN 256
#define TK 64                      // K elems per stage (128B per row)
#define NSTAGE 3
#define NK (KK / TK)               // 64

#define A_STAGE_BYTES (TM * TK * 2)            // 16384
#define B_STAGE_BYTES (TN * TK * 2)            // 32768
#define SMEM_TOTAL (NSTAGE * (A_STAGE_BYTES + B_STAGE_BYTES))  // 147456

__device__ __align__(1024) __half g_xh[(size_t)MM * KK];   // x as fp16, [M][K]
__device__ __align__(1024) __half g_sh[(size_t)NN * KK];   // sign(W)^T fp16, [N][K]

// ---------------------------------------------------------------------------
__device__ __forceinline__ uint32_t smem_u32(const void* p) {
    uint32_t a;
    asm("{ .reg .u64 t; cvta.to.shared.u64 t, %1; cvt.u32.u64 %0, t; }"
        : "=r"(a) : "l"(p));
    return a;
}

#define CP_ASYNC_CG(dst, src) \
    asm volatile("cp.async.cg.shared.global [%0], [%1], 16;" \
        :: "r"((uint32_t)(dst)), "l"(src) : "memory")
#define CP_COMMIT() asm volatile("cp.async.commit_group;" ::: "memory")
#define CP_WAIT(n)  asm volatile("cp.async.wait_group %0;" :: "n"(n) : "memory")

__device__ __forceinline__ void ldsm4(uint32_t* r, uint32_t addr) {
    asm volatile("ldmatrix.sync.aligned.m8n8.x4.shared.b16 {%0,%1,%2,%3}, [%4];"
        : "=r"(r[0]), "=r"(r[1]), "=r"(r[2]), "=r"(r[3]) : "r"(addr));
}

__device__ __forceinline__ void mma16816(float* c, const uint32_t* a, const uint32_t* b) {
    asm volatile(
        "mma.sync.aligned.m16n8k16.row.col.f32.f16.f16.f32 "
        "{%0,%1,%2,%3}, {%4,%5,%6,%7}, {%8,%9}, {%0,%1,%2,%3};"
        : "+f"(c[0]), "+f"(c[1]), "+f"(c[2]), "+f"(c[3])
        : "r"(a[0]), "r"(a[1]), "r"(a[2]), "r"(a[3]), "r"(b[0]), "r"(b[1]));
}

// ---------------------------------------------------------------------------
struct h8_t { __half2 a, b, c, d; };   // 16B

__global__ void k_cvt_x(const float4* __restrict__ x, h8_t* __restrict__ o, int n8) {
    int i = blockIdx.x * blockDim.x + threadIdx.x;
    if (i < n8) {
        float4 v0 = x[2 * i];
        float4 v1 = x[2 * i + 1];
        h8_t h;
        h.a = __floats2half2_rn(v0.x, v0.y);
        h.b = __floats2half2_rn(v0.z, v0.w);
        h.c = __floats2half2_rn(v1.x, v1.y);
        h.d = __floats2half2_rn(v1.z, v1.w);
        o[i] = h;
    }
}

__global__ void k_sign_t(const float* __restrict__ W, __half* __restrict__ o) {
    __shared__ float t[32][33];
    int n0 = blockIdx.x * 32, k0 = blockIdx.y * 32;
    int tx = threadIdx.x, ty = threadIdx.y;
#pragma unroll
    for (int j = 0; j < 32; j += 8)
        t[ty + j][tx] = W[(size_t)(k0 + ty + j) * NN + n0 + tx];
    __syncthreads();
#pragma unroll
    for (int j = 0; j < 32; j += 8) {
        float v = t[tx][ty + j];
        float s = (v > 0.f) ? 1.f : ((v < 0.f) ? -1.f : 0.f);
        o[(size_t)(n0 + ty + j) * KK + k0 + tx] = __float2half(s);
    }
}

// ---------------------------------------------------------------------------
// GEMM: 128x256 CTA tile, 8 warps (2M x 4N), warp tile 64x64, 3-stage cp.async
// ---------------------------------------------------------------------------
__global__ __launch_bounds__(256, 1) void gemm_kernel(float* __restrict__ out) {
    extern __shared__ char smem[];
    const uint32_t sA0 = smem_u32(smem);
    const uint32_t sB0 = sA0 + NSTAGE * A_STAGE_BYTES;

    const int tid = threadIdx.x;
    const int wid = tid >> 5;
    const int lane = tid & 31;
    const int wm = wid & 1;
    const int wn = wid >> 1;

    const int TILES_N = NN / TN;   // 16
    const int GROUP_M = 8;
    int bid = blockIdx.x;
    int group = bid / (GROUP_M * TILES_N);
    int rem = bid % (GROUP_M * TILES_N);
    int pm = group * GROUP_M + (rem % GROUP_M);
    int pn = rem / GROUP_M;
    const int m0 = pm * TM;
    const int n0 = pn * TN;

    const __half* gA = g_xh + (size_t)m0 * KK;
    const __half* gB = g_sh + (size_t)n0 * KK;

    auto load_stage = [&](int s, int it) {
        uint32_t sa = sA0 + s * A_STAGE_BYTES;
        uint32_t sb = sB0 + s * B_STAGE_BYTES;
        const __half* ga = gA + (size_t)it * TK;
        const __half* gb = gB + (size_t)it * TK;
#pragma unroll
        for (int i = 0; i < 4; ++i) {
            int idx = tid + i * 256;
            int row = idx >> 3, c = idx & 7;
            int sc = c ^ (row & 7);
            CP_ASYNC_CG(sa + row * 128 + sc * 16, ga + (size_t)row * KK + c * 8);
        }
#pragma unroll
        for (int i = 0; i < 8; ++i) {
            int idx = tid + i * 256;
            int row = idx >> 3, c = idx & 7;
            int sc = c ^ (row & 7);
            CP_ASYNC_CG(sb + row * 128 + sc * 16, gb + (size_t)row * KK + c * 8);
        }
    };

    // fragment loaders (double-buffered across ks)
    const int a_row_base = wm * 64 + (lane & 15);
    const int a_hi = lane >> 4;                       // 0/1 -> k-chunk parity
    const int b_n_base = wn * 64 + (lane & 7) + ((lane >> 4) << 3);
    const int b_hi = (lane >> 3) & 1;

    auto load_a = [&](uint32_t sa, int ks, uint32_t (*a)[4]) {
#pragma unroll
        for (int mt = 0; mt < 4; ++mt) {
            int row = a_row_base + mt * 16;
            int ch = ks * 2 + a_hi;
            ldsm4(a[mt], sa + row * 128 + ((ch ^ (row & 7)) << 4));
        }
    };
    auto load_b = [&](uint32_t sb, int ks, uint32_t (*b)[4]) {
#pragma unroll
        for (int bq = 0; bq < 4; ++bq) {
            int n = b_n_base + bq * 16;
            int ch = ks * 2 + b_hi;
            ldsm4(b[bq], sb + n * 128 + ((ch ^ (n & 7)) << 4));
        }
    };

    float acc[4][8][4];
#pragma unroll
    for (int mt = 0; mt < 4; ++mt)
#pragma unroll
        for (int nf = 0; nf < 8; ++nf)
#pragma unroll
            for (int v = 0; v < 4; ++v) acc[mt][nf][v] = 0.f;

#pragma unroll
    for (int s = 0; s < NSTAGE - 1; ++s) {
        load_stage(s, s);
        CP_COMMIT();
    }

    int s_cur = 0;      // stage consumed this iteration
    int s_nxt = NSTAGE - 1;  // stage to fill this iteration

    for (int it = 0; it < NK; ++it) {
        CP_WAIT(NSTAGE - 2);
        __syncthreads();   // single sync: orders prev-iter LDSM before refill below

        int nx = it + NSTAGE - 1;
        if (nx < NK) load_stage(s_nxt, nx);
        CP_COMMIT();

        const uint32_t sa = sA0 + s_cur * A_STAGE_BYTES;
        const uint32_t sb = sB0 + s_cur * B_STAGE_BYTES;

        uint32_t a[2][4][4], b[2][4][4];
        load_a(sa, 0, a[0]);
        load_b(sb, 0, b[0]);
#pragma unroll
        for (int ks = 0; ks < 4; ++ks) {
            int cur = ks & 1, nxt = cur ^ 1;
            if (ks < 3) {
                load_a(sa, ks + 1, a[nxt]);
                load_b(sb, ks + 1, b[nxt]);
            }
#pragma unroll
            for (int mt = 0; mt < 4; ++mt)
#pragma unroll
                for (int nf = 0; nf < 8; ++nf)
                    mma16816(acc[mt][nf], a[cur][mt], &b[cur][nf >> 1][(nf & 1) * 2]);
        }

        if (++s_cur == NSTAGE) s_cur = 0;
        if (++s_nxt == NSTAGE) s_nxt = 0;
    }

    // epilogue
#pragma unroll
    for (int mt = 0; mt < 4; ++mt) {
        int r0 = m0 + wm * 64 + mt * 16 + (lane >> 2);
#pragma unroll
        for (int nf = 0; nf < 8; ++nf) {
            int c0 = n0 + wn * 64 + nf * 8 + (lane & 3) * 2;
            float2 v0 = make_float2(acc[mt][nf][0], acc[mt][nf][1]);
            float2 v1 = make_float2(acc[mt][nf][2], acc[mt][nf][3]);
            *reinterpret_cast<float2*>(out + (size_t)r0 * NN + c0) = v0;
            *reinterpret_cast<float2*>(out + (size_t)(r0 + 8) * NN + c0) = v1;
        }
    }
}

// ---------------------------------------------------------------------------
extern "C" void kernel_launch(void* const* d_in, const int* in_sizes, int n_in,
                              void* d_out, int out_size) {
    const float* x;
    const float* W;
    if (in_sizes[0] == MM * KK) {
        x = (const float*)d_in[0];
        W = (const float*)d_in[1];
    } else {
        x = (const float*)d_in[1];
        W = (const float*)d_in[0];
    }

    void* xh_ptr = nullptr;
    void* sh_ptr = nullptr;
    cudaGetSymbolAddress(&xh_ptr, g_xh);
    cudaGetSymbolAddress(&sh_ptr, g_sh);

    {
        int n8 = MM * KK / 8;
        k_cvt_x<<<(n8 + 255) / 256, 256>>>((const float4*)x, (h8_t*)xh_ptr, n8);
        dim3 g(NN / 32, KK / 32), b(32, 8);
        k_sign_t<<<g, b>>>(W, (__half*)sh_ptr);
    }

    cudaFuncSetAttribute(gemm_kernel, cudaFuncAttributeMaxDynamicSharedMemorySize, SMEM_TOTAL);
    int n_tiles = (MM / TM) * (NN / TN);   // 1024
    gemm_kernel<<<n_tiles, 256, SMEM_TOTAL>>>((float*)d_out);
}

// round 5
// speedup vs baseline: 1.0514x; 1.0183x over previous
#include <cuda_runtime.h>
#include <cuda_fp16.h>
#include <cstdint>

// ============================================================================
// y[8192,4096] = x[8192,4096] @ sign(W)[4096,4096], fp32 in/out.
// Plain-sm_103 target (no tcgen05). Ampere-style pipelined HMMA GEMM.
// R5: TK=128 / 2-stage (halves loop fixed costs), wider sign-transpose.
// CTA tile 128x256, warp tile 64x64 (best bytes/HMMA found so far).
// ============================================================================

#define MM 8192
#define NN 4096
#define KK 4096

#define TM 128
#define TN 256
#define TK 128                     // K elems per stage (256B per row)
#define NSTAGE 2
#define NK (KK / TK)               // 32

#define A_STAGE_BYTES (TM * TK * 2)            // 32768
#define B_STAGE_BYTES (TN * TK * 2)            // 65536
#define SMEM_TOTAL (NSTAGE * (A_STAGE_BYTES + B_STAGE_BYTES))  // 196608

__device__ __align__(1024) __half g_xh[(size_t)MM * KK];   // x as fp16, [M][K]
__device__ __align__(1024) __half g_sh[(size_t)NN * KK];   // sign(W)^T fp16, [N][K]

// ---------------------------------------------------------------------------
__device__ __forceinline__ uint32_t smem_u32(const void* p) {
    uint32_t a;
    asm("{ .reg .u64 t; cvta.to.shared.u64 t, %1; cvt.u32.u64 %0, t; }"
        : "=r"(a) : "l"(p));
    return a;
}

#define CP_ASYNC_CG(dst, src) \
    asm volatile("cp.async.cg.shared.global [%0], [%1], 16;" \
        :: "r"((uint32_t)(dst)), "l"(src) : "memory")
#define CP_COMMIT() asm volatile("cp.async.commit_group;" ::: "memory")
#define CP_WAIT(n)  asm volatile("cp.async.wait_group %0;" :: "n"(n) : "memory")

__device__ __forceinline__ void ldsm4(uint32_t* r, uint32_t addr) {
    asm volatile("ldmatrix.sync.aligned.m8n8.x4.shared.b16 {%0,%1,%2,%3}, [%4];"
        : "=r"(r[0]), "=r"(r[1]), "=r"(r[2]), "=r"(r[3]) : "r"(addr));
}

__device__ __forceinline__ void mma16816(float* c, const uint32_t* a, const uint32_t* b) {
    asm volatile(
        "mma.sync.aligned.m16n8k16.row.col.f32.f16.f16.f32 "
        "{%0,%1,%2,%3}, {%4,%5,%6,%7}, {%8,%9}, {%0,%1,%2,%3};"
        : "+f"(c[0]), "+f"(c[1]), "+f"(c[2]), "+f"(c[3])
        : "r"(a[0]), "r"(a[1]), "r"(a[2]), "r"(a[3]), "r"(b[0]), "r"(b[1]));
}

// ---------------------------------------------------------------------------
struct h8_t { __half2 a, b, c, d; };   // 16B

__global__ void k_cvt_x(const float4* __restrict__ x, h8_t* __restrict__ o, int n8) {
    int i = blockIdx.x * blockDim.x + threadIdx.x;
    if (i < n8) {
        float4 v0 = x[2 * i];
        float4 v1 = x[2 * i + 1];
        h8_t h;
        h.a = __floats2half2_rn(v0.x, v0.y);
        h.b = __floats2half2_rn(v0.z, v0.w);
        h.c = __floats2half2_rn(v1.x, v1.y);
        h.d = __floats2half2_rn(v1.z, v1.w);
        o[i] = h;
    }
}

// o[n][k] = sign(W[k][n]) fp16; 64x64 tiles -> 128B coalesced output rows
__global__ void k_sign_t(const float* __restrict__ W, __half* __restrict__ o) {
    __shared__ float t[64][65];
    int n0 = blockIdx.x * 64, k0 = blockIdx.y * 64;
    int tx = threadIdx.x, ty = threadIdx.y;    // (64, 4)
#pragma unroll
    for (int j = 0; j < 64; j += 4)
        t[ty + j][tx] = W[(size_t)(k0 + ty + j) * NN + n0 + tx];
    __syncthreads();
#pragma unroll
    for (int j = 0; j < 64; j += 4) {
        float v = t[tx][ty + j];
        float s = (v > 0.f) ? 1.f : ((v < 0.f) ? -1.f : 0.f);
        o[(size_t)(n0 + ty + j) * KK + k0 + tx] = __float2half(s);
    }
}

// ---------------------------------------------------------------------------
// GEMM: 128x256 CTA tile, 8 warps (2M x 4N), warp tile 64x64, 2-stage TK=128
// ---------------------------------------------------------------------------
__global__ __launch_bounds__(256, 1) void gemm_kernel(float* __restrict__ out) {
    extern __shared__ char smem[];
    const uint32_t sA0 = smem_u32(smem);
    const uint32_t sB0 = sA0 + NSTAGE * A_STAGE_BYTES;

    const int tid = threadIdx.x;
    const int wid = tid >> 5;
    const int lane = tid & 31;
    const int wm = wid & 1;
    const int wn = wid >> 1;

    const int TILES_N = NN / TN;   // 16
    const int GROUP_M = 8;
    int bid = blockIdx.x;
    int group = bid / (GROUP_M * TILES_N);
    int rem = bid % (GROUP_M * TILES_N);
    int pm = group * GROUP_M + (rem % GROUP_M);
    int pn = rem / GROUP_M;
    const int m0 = pm * TM;
    const int n0 = pn * TN;

    const __half* gA = g_xh + (size_t)m0 * KK;
    const __half* gB = g_sh + (size_t)n0 * KK;

    // stage loader: rows of 256B (16 chunks of 16B), XOR-swizzle low 3 bits
    auto load_stage = [&](int s, int it) {
        uint32_t sa = sA0 + s * A_STAGE_BYTES;
        uint32_t sb = sB0 + s * B_STAGE_BYTES;
        const __half* ga = gA + (size_t)it * TK;
        const __half* gb = gB + (size_t)it * TK;
#pragma unroll
        for (int i = 0; i < 8; ++i) {                 // A: 2048 chunks
            int idx = tid + i * 256;
            int row = idx >> 4, c = idx & 15;
            int sc = c ^ (row & 7);
            CP_ASYNC_CG(sa + row * 256 + sc * 16, ga + (size_t)row * KK + c * 8);
        }
#pragma unroll
        for (int i = 0; i < 16; ++i) {                // B: 4096 chunks
            int idx = tid + i * 256;
            int row = idx >> 4, c = idx & 15;
            int sc = c ^ (row & 7);
            CP_ASYNC_CG(sb + row * 256 + sc * 16, gb + (size_t)row * KK + c * 8);
        }
    };

    const int a_row_base = wm * 64 + (lane & 15);
    const int a_hi = lane >> 4;
    const int b_n_base = wn * 64 + (lane & 7) + ((lane >> 4) << 3);
    const int b_hi = (lane >> 3) & 1;

    auto load_a = [&](uint32_t sa, int ks, uint32_t (*a)[4]) {
#pragma unroll
        for (int mt = 0; mt < 4; ++mt) {
            int row = a_row_base + mt * 16;
            int ch = ks * 2 + a_hi;
            ldsm4(a[mt], sa + row * 256 + ((ch ^ (row & 7)) << 4));
        }
    };
    auto load_b = [&](uint32_t sb, int ks, uint32_t (*b)[4]) {
#pragma unroll
        for (int bq = 0; bq < 4; ++bq) {
            int n = b_n_base + bq * 16;
            int ch = ks * 2 + b_hi;
            ldsm4(b[bq], sb + n * 256 + ((ch ^ (n & 7)) << 4));
        }
    };

    float acc[4][8][4];
#pragma unroll
    for (int mt = 0; mt < 4; ++mt)
#pragma unroll
        for (int nf = 0; nf < 8; ++nf)
#pragma unroll
            for (int v = 0; v < 4; ++v) acc[mt][nf][v] = 0.f;

    load_stage(0, 0);
    CP_COMMIT();

    for (int it = 0; it < NK; ++it) {
        CP_WAIT(0);
        __syncthreads();   // stage `it` ready; prev compute done -> other buffer free

        if (it + 1 < NK) load_stage((it + 1) & 1, it + 1);
        CP_COMMIT();

        const int s = it & 1;
        const uint32_t sa = sA0 + s * A_STAGE_BYTES;
        const uint32_t sb = sB0 + s * B_STAGE_BYTES;

        uint32_t a[2][4][4], b[2][4][4];
        load_a(sa, 0, a[0]);
        load_b(sb, 0, b[0]);
#pragma unroll
        for (int ks = 0; ks < 8; ++ks) {
            int cur = ks & 1, nxt = cur ^ 1;
            if (ks < 7) {
                load_a(sa, ks + 1, a[nxt]);
                load_b(sb, ks + 1, b[nxt]);
            }
#pragma unroll
            for (int mt = 0; mt < 4; ++mt)
#pragma unroll
                for (int nf = 0; nf < 8; ++nf)
                    mma16816(acc[mt][nf], a[cur][mt], &b[cur][nf >> 1][(nf & 1) * 2]);
        }
    }

    // epilogue
#pragma unroll
    for (int mt = 0; mt < 4; ++mt) {
        int r0 = m0 + wm * 64 + mt * 16 + (lane >> 2);
#pragma unroll
        for (int nf = 0; nf < 8; ++nf) {
            int c0 = n0 + wn * 64 + nf * 8 + (lane & 3) * 2;
            float2 v0 = make_float2(acc[mt][nf][0], acc[mt][nf][1]);
            float2 v1 = make_float2(acc[mt][nf][2], acc[mt][nf][3]);
            *reinterpret_cast<float2*>(out + (size_t)r0 * NN + c0) = v0;
            *reinterpret_cast<float2*>(out + (size_t)(r0 + 8) * NN + c0) = v1;
        }
    }
}

// ---------------------------------------------------------------------------
extern "C" void kernel_launch(void* const* d_in, const int* in_sizes, int n_in,
                              void* d_out, int out_size) {
    const float* x;
    const float* W;
    if (in_sizes[0] == MM * KK) {
        x = (const float*)d_in[0];
        W = (const float*)d_in[1];
    } else {
        x = (const float*)d_in[1];
        W = (const float*)d_in[0];
    }

    void* xh_ptr = nullptr;
    void* sh_ptr = nullptr;
    cudaGetSymbolAddress(&xh_ptr, g_xh);
    cudaGetSymbolAddress(&sh_ptr, g_sh);

    {
        int n8 = MM * KK / 8;
        k_cvt_x<<<(n8 + 255) / 256, 256>>>((const float4*)x, (h8_t*)xh_ptr, n8);
        dim3 g(NN / 64, KK / 64), b(64, 4);
        k_sign_t<<<g, b>>>(W, (__half*)sh_ptr);
    }

    cudaFuncSetAttribute(gemm_kernel, cudaFuncAttributeMaxDynamicSharedMemorySize, SMEM_TOTAL);
    int n_tiles = (MM / TM) * (NN / TN);   // 1024
    gemm_kernel<<<n_tiles, 256, SMEM_TOTAL>>>((float*)d_out);
}